// round 16
// baseline (speedup 1.0000x reference)
#include <cuda_runtime.h>
#include <math.h>

#define RES      256
#define NTRI     1000
#define NBATCH   2
#define NBT      (NBATCH * NTRI)
#define EPSF     1e-8f
#define NPIX     (RES * RES)
#define TIL      8                    // tile edge (px)
#define TPA      (RES / TIL)          // 32 tiles per axis
#define NTILE    (TPA * TPA)          // 1024 tiles per batch
#define NSEG     8                    // triangle-list segments per tile
#define SEGCAP   128                  // >= ceil(NTRI/NSEG)
#define BLKSPT   (NSEG / 2)           // gather blocks per tile (2 warps = 2 segs each)

// per-(b,t) params: q0={A0,B0,C0,A1} q1={B1,C1,A2,B2} q2={C2,mn,inv,unused}
__device__ float4 g_q[NBT * 3];
__device__ int4   g_bb[NBT];
// per-(b,tile) triangle lists (ascending t, order-preserving)
__device__ int    g_cnt[NBATCH * NTILE];
__device__ int    g_list[NBATCH * NTILE * NTRI];
// split-K partials: [(b*NSEG+s)*NTILE + tile]*64 + px   (4 MB, overwritten each launch)
__device__ float  g_part[NBATCH * NSEG * NTILE * 64];
// per-(b,tile) arrival counters; zero at load, reset by finisher each launch
__device__ int    g_done[NBATCH * NTILE];

struct Coef { float A0,B0,C0, A1,B1,C1, A2,B2,C2; };

__device__ __forceinline__ float eval_s(const Coef& c, float fx, float fy)
{
    float t0 = fmaxf(fmaf(c.C0, fy, fmaf(c.B0, fx, c.A0)), 0.0f);
    float t1 = fmaxf(fmaf(c.C1, fy, fmaf(c.B1, fx, c.A1)), 0.0f);
    float t2 = fmaxf(fmaf(c.C2, fy, fmaf(c.B2, fx, c.A2)), 0.0f);
    return t0 * t1 * t2;
}

// (5,4) continued-fraction Pade tanh, err <= ~2.4e-5 on [0, 1.05]
__device__ __forceinline__ float tanh_pade(float x)
{
    float t   = x * x;
    float num = fmaf(t, fmaf(t, 1.0f, 105.0f), 945.0f);
    float den = fmaf(t, fmaf(t, 15.0f, 420.0f), 945.0f);
    return x * __fdividef(num, den);
}

// exact grid max over row y within [bb.x, bb.y] (log-concave -> candidates)
__device__ float row_max(const Coef& c, const Coef& n, const int4 bb, int y)
{
    const float fy = (float)y;
    float a0 = fmaf(n.C0, fy, n.A0);
    float a1 = fmaf(n.C1, fy, n.A1);
    float a2 = fmaf(n.C2, fy, n.A2);

    float lo = (float)bb.x, hi = (float)bb.y;
    bool ok = true;
    if (n.B0 >  1e-25f)      lo = fmaxf(lo, -__fdividef(a0, n.B0));
    else if (n.B0 < -1e-25f) hi = fminf(hi, -__fdividef(a0, n.B0));
    else                     ok = ok && (a0 > 0.0f);
    if (n.B1 >  1e-25f)      lo = fmaxf(lo, -__fdividef(a1, n.B1));
    else if (n.B1 < -1e-25f) hi = fminf(hi, -__fdividef(a1, n.B1));
    else                     ok = ok && (a1 > 0.0f);
    if (n.B2 >  1e-25f)      lo = fmaxf(lo, -__fdividef(a2, n.B2));
    else if (n.B2 < -1e-25f) hi = fminf(hi, -__fdividef(a2, n.B2));
    else                     ok = ok && (a2 > 0.0f);

    float clo = ceilf(lo), chi = floorf(hi);
    if (!ok || clo > chi) return 0.0f;

    float q2 = 3.0f * n.B0 * n.B1 * n.B2;
    float q1 = 2.0f * (n.B0*n.B1*a2 + n.B0*n.B2*a1 + n.B1*n.B2*a0);
    float q0 = n.B0*a1*a2 + n.B1*a0*a2 + n.B2*a0*a1;

    float xc1 = 0.5f * (clo + chi), xc2 = xc1;
    if (fabsf(q2) > 1e-30f) {
        float disc = fmaf(q1, q1, -4.0f * q2 * q0);
        float sq   = sqrtf(fmaxf(disc, 0.0f));
        float i2   = __fdividef(0.5f, q2);
        xc1 = (-q1 + sq) * i2;
        xc2 = (-q1 - sq) * i2;
    } else if (fabsf(q1) > 1e-30f) {
        xc1 = xc2 = -__fdividef(q0, q1);
    }

    float f1 = floorf(xc1), f2 = floorf(xc2);
    float cand[6] = { clo, chi, f1, f1 + 1.0f, f2, f2 + 1.0f };
    float m = 0.0f;
    #pragma unroll
    for (int i = 0; i < 6; i++) {
        float x = fminf(fmaxf(cand[i], clo), chi);   // NaN-safe
        m = fmaxf(m, eval_s(c, x, fy));
    }
    return m;
}

// ---------------------------------------------------------------------------
// Kernel 1: one block (64 thr = 2 warps) per (b,t). Both warps redundantly
// compute coefficients; rows split across all 64 lanes (halves serial chain).
// ---------------------------------------------------------------------------
__global__ void __launch_bounds__(64) setup_kernel(const float* __restrict__ meshes,
                                                   const float* __restrict__ K,
                                                   const int*   __restrict__ model_idxs,
                                                   const float* __restrict__ poses)
{
    const int bt  = blockIdx.x;
    const int tid = threadIdx.x;
    const int lane = tid & 31;
    const int w    = tid >> 5;
    const int b = bt / NTRI;
    const int t = bt - b * NTRI;

    float M[12];
    const float* cam = poses + b * 12;
    #pragma unroll
    for (int r = 0; r < 3; r++)
        #pragma unroll
        for (int cc = 0; cc < 4; cc++) {
            float s = 0.0f;
            #pragma unroll
            for (int k = 0; k < 3; k++)
                s += K[r * 3 + k] * cam[k * 4 + cc];
            M[r * 4 + cc] = s;
        }

    const float* mesh = meshes + ((size_t)model_idxs[b] * NTRI + t) * 9;
    float vx[3], vy[3];
    #pragma unroll
    for (int j = 0; j < 3; j++) {
        float X = mesh[j*3+0], Y = mesh[j*3+1], Z = mesh[j*3+2];
        float x = M[0]*X + M[1]*Y + M[2] *Z + M[3];
        float y = M[4]*X + M[5]*Y + M[6] *Z + M[7];
        float wq = M[8]*X + M[9]*Y + M[10]*Z + M[11];
        float iw = 1.0f / (wq + EPSF);
        vx[j] = x * iw;  vy[j] = y * iw;
    }

    const float e0x = vx[1]-vx[0], e0y = vy[1]-vy[0];
    const float e1x = vx[2]-vx[1], e1y = vy[2]-vy[1];
    const float e2x = vx[0]-vx[2], e2y = vy[0]-vy[2];
    const float N = e0x * e2y - e0y * e2x + EPSF;

    Coef c;
    c.A0 = N*(e0x*vy[0]-e0y*vx[0]); c.B0 =  N*e0y; c.C0 = -N*e0x;
    c.A1 = N*(e1x*vy[1]-e1y*vx[1]); c.B1 =  N*e1y; c.C1 = -N*e1x;
    c.A2 = N*(e2x*vy[2]-e2y*vx[2]); c.B2 =  N*e2y; c.C2 = -N*e2x;

    bool inter = true;
    #pragma unroll
    for (int k = 0; k < 4; k++) {
        float cx = (k & 1) ? (float)(RES-1) : 0.0f;
        float cy = (k & 2) ? (float)(RES-1) : 0.0f;
        inter = inter && (fmaf(c.C0, cy, fmaf(c.B0, cx, c.A0)) > 0.0f)
                      && (fmaf(c.C1, cy, fmaf(c.B1, cx, c.A1)) > 0.0f)
                      && (fmaf(c.C2, cy, fmaf(c.B2, cx, c.A2)) > 0.0f);
    }

    float fx0 = fminf(fminf(vx[0],vx[1]),vx[2]) - 1.0f;
    float fx1 = fmaxf(fmaxf(vx[0],vx[1]),vx[2]) + 1.0f;
    float fy0 = fminf(fminf(vy[0],vy[1]),vy[2]) - 1.0f;
    float fy1 = fmaxf(fmaxf(vy[0],vy[1]),vy[2]) + 1.0f;
    bool safe = isfinite(fx0) && isfinite(fx1) && isfinite(fy0) && isfinite(fy1)
                && fabsf(N) > 1e-6f;
    int4 bb;
    if (safe) {
        int x0 = (fx0 < 0.0f) ? 0 : ((fx0 > (float)(RES-1)) ? RES : (int)fx0);
        int x1 = (fx1 > (float)(RES-1)) ? (RES-1) : ((fx1 < 0.0f) ? -1 : (int)fx1);
        int y0 = (fy0 < 0.0f) ? 0 : ((fy0 > (float)(RES-1)) ? RES : (int)fy0);
        int y1 = (fy1 > (float)(RES-1)) ? (RES-1) : ((fy1 < 0.0f) ? -1 : (int)fy1);
        if (x0 > x1 || y0 > y1) { x0 = RES; x1 = -1; y0 = RES; y1 = -1; }
        bb = make_int4(x0, x1, y0, y1);
    } else {
        bb = make_int4(0, RES-1, 0, RES-1);
    }

    float kap = 0.0f;
    kap = fmaxf(kap, fabsf(c.A0)); kap = fmaxf(kap, 256.0f*fabsf(c.B0)); kap = fmaxf(kap, 256.0f*fabsf(c.C0));
    kap = fmaxf(kap, fabsf(c.A1)); kap = fmaxf(kap, 256.0f*fabsf(c.B1)); kap = fmaxf(kap, 256.0f*fabsf(c.C1));
    kap = fmaxf(kap, fabsf(c.A2)); kap = fmaxf(kap, 256.0f*fabsf(c.B2)); kap = fmaxf(kap, 256.0f*fabsf(c.C2));
    float rk = (kap > 1e-30f) ? (1.0f / kap) : 0.0f;
    Coef n;
    n.A0 = c.A0*rk; n.B0 = c.B0*rk; n.C0 = c.C0*rk;
    n.A1 = c.A1*rk; n.B1 = c.B1*rk; n.C1 = c.C1*rk;
    n.A2 = c.A2*rk; n.B2 = c.B2*rk; n.C2 = c.C2*rk;

    // rows split across all 64 lanes of the block
    float mx = 0.0f;
    for (int y = bb.z + tid; y <= bb.w; y += 64)
        mx = fmaxf(mx, row_max(c, n, bb, y));
    #pragma unroll
    for (int o = 16; o > 0; o >>= 1)
        mx = fmaxf(mx, __shfl_xor_sync(0xffffffffu, mx, o));

    __shared__ float sm[2];
    if (lane == 0) sm[w] = mx;
    __syncthreads();

    if (tid == 0) {
        float rmx = fmaxf(sm[0], sm[1]);
        float mn = 0.0f;
        if (inter) {   // quasi-concave => grid min at an image corner
            const float e = (float)(RES - 1);
            mn = eval_s(c, 0.0f, 0.0f);
            mn = fminf(mn, eval_s(c, e, 0.0f));
            mn = fminf(mn, eval_s(c, 0.0f, e));
            mn = fminf(mn, eval_s(c, e, e));
        }
        float inv = 1.0f / (rmx - mn + EPSF);
        g_q[bt*3+0] = make_float4(c.A0, c.B0, c.C0, c.A1);
        g_q[bt*3+1] = make_float4(c.B1, c.C1, c.A2, c.B2);
        g_q[bt*3+2] = make_float4(c.C2, mn,   inv,  0.0f);
        g_bb[bt]    = bb;
    }
}

// ---------------------------------------------------------------------------
// Kernel 2: deterministic, order-preserving 8x8 tile binning (unchanged).
// ---------------------------------------------------------------------------
__global__ void __launch_bounds__(256) bin_kernel()
{
    const int gw = (blockIdx.x * blockDim.x + threadIdx.x) >> 5;
    if (gw >= NBATCH * NTILE) return;
    const int lane = threadIdx.x & 31;

    const int b  = gw / NTILE;
    const int tt = gw - b * NTILE;
    const int xlo = (tt >> 5) * TIL, xhi = xlo + TIL - 1;
    const int ylo = (tt & 31) * TIL, yhi = ylo + TIL - 1;

    const int4* __restrict__ bb = g_bb + b * NTRI;
    int* __restrict__ list = g_list + (size_t)gw * NTRI;

    int cnt = 0;
    for (int base = 0; base < NTRI; base += 32) {
        const int t = base + lane;
        bool ok = false;
        if (t < NTRI) {
            int4 B = bb[t];
            ok = (B.x <= xhi) && (B.y >= xlo) && (B.z <= yhi) && (B.w >= ylo);
        }
        unsigned m = __ballot_sync(0xffffffffu, ok);
        if (ok) list[cnt + __popc(m & ((1u << lane) - 1u))] = t;
        cnt += __popc(m);
    }
    if (lane == 0) g_cnt[gw] = cnt;
}

// ---------------------------------------------------------------------------
// Kernel 3: split-K gather with fused finish.
// grid = (NTILE, BLKSPT, NBATCH), block = 64 (2 warps). Warp w handles
// segment seg = blockIdx.y*2 + w; each lane owns 2 y-adjacent pixels.
// Last-arriving block per tile sums the NSEG partials in fixed ascending
// order (single block, fixed order => deterministic) and writes output.
// ---------------------------------------------------------------------------
__global__ void __launch_bounds__(64) gather_kernel(float* __restrict__ out)
{
    __shared__ float4 sQ[2][SEGCAP * 3];
    __shared__ int sLast;

    const int tt   = blockIdx.x;
    const int b    = blockIdx.z;
    const int tid  = threadIdx.x;
    const int lane = tid & 31;
    const int w    = tid >> 5;
    const int seg  = (int)blockIdx.y * 2 + w;

    const int gw  = b * NTILE + tt;
    const int cnt = g_cnt[gw];
    const int len = (cnt + NSEG - 1) / NSEG;
    const int s0  = min(cnt, seg * len);
    const int m   = min(cnt, s0 + len) - s0;

    // stage this warp's segment
    if (m > 0) {
        const int* __restrict__ list = g_list + (size_t)gw * NTRI + s0;
        for (int i = lane; i < m; i += 32) {
            const int t3 = (b * NTRI + list[i]) * 3;
            sQ[w][i*3+0] = g_q[t3+0];
            sQ[w][i*3+1] = g_q[t3+1];
            sQ[w][i*3+2] = g_q[t3+2];
        }
    }
    __syncwarp();

    // 2 pixels per lane: local px = lane>>2, local py = 2*(lane&3), +1
    const float fx  = (float)((tt >> 5) * TIL + (lane >> 2));
    const float fy0 = (float)((tt & 31) * TIL + 2 * (lane & 3));
    const float fy1 = fy0 + 1.0f;

    float acc0 = 0.0f, acc1 = 0.0f;
    const float4* __restrict__ q = sQ[w];
    #pragma unroll 2
    for (int i = 0; i < m; i++) {
        float4 q0 = q[i*3+0], q1 = q[i*3+1], q2 = q[i*3+2];
        // shared row constants (A + B*x)
        float r0 = fmaf(q0.y, fx, q0.x);
        float r1 = fmaf(q1.x, fx, q0.w);
        float r2 = fmaf(q1.w, fx, q1.z);
        // two independent pixel chains
        float u00 = fmaxf(fmaf(q0.z, fy0, r0), 0.0f);
        float u01 = fmaxf(fmaf(q0.z, fy1, r0), 0.0f);
        float u10 = fmaxf(fmaf(q1.y, fy0, r1), 0.0f);
        float u11 = fmaxf(fmaf(q1.y, fy1, r1), 0.0f);
        float u20 = fmaxf(fmaf(q2.x, fy0, r2), 0.0f);
        float u21 = fmaxf(fmaf(q2.x, fy1, r2), 0.0f);
        float d0  = u00 * u10 * u20 - q2.y;
        float d1  = u01 * u11 * u21 - q2.y;
        if (d0 > 0.0f) acc0 += tanh_pade(d0 * q2.z);
        if (d1 > 0.0f) acc1 += tanh_pade(d1 * q2.z);
    }

    // write this segment's partial (px-major within tile: idx = x*8 + y)
    const int p0 = (lane >> 2) * TIL + 2 * (lane & 3);
    float* part = g_part + (((size_t)b * NSEG + seg) * NTILE + tt) * 64;
    part[p0]     = acc0;
    part[p0 + 1] = acc1;

    // ---- fused finish: last block of this tile reduces all segments -------
    __threadfence();
    __syncthreads();
    if (tid == 0) {
        int old = atomicAdd(&g_done[gw], 1);
        sLast = (old == BLKSPT - 1);
    }
    __syncthreads();

    if (sLast) {
        __threadfence();                    // acquire: partials visible
        // thread j sums pixel j over segments 0..NSEG-1 in fixed order
        float s = 0.0f;
        #pragma unroll
        for (int sg = 0; sg < NSEG; sg++)
            s += g_part[(((size_t)b * NSEG + sg) * NTILE + tt) * 64 + tid];

        const int px = (tt >> 5) * TIL + (tid >> 3);
        const int py = (tt & 31) * TIL + (tid & 7);
        out[(size_t)b * NPIX + px * RES + py] = s;

        if (tid == 0) g_done[gw] = 0;       // reset for next graph replay
    }
}

// ---------------------------------------------------------------------------
extern "C" void kernel_launch(void* const* d_in, const int* in_sizes, int n_in,
                              void* d_out, int out_size)
{
    const float* meshes = (const float*)d_in[0];
    const float* K      = (const float*)d_in[1];
    const int*   idxs   = (const int*)  d_in[2];
    const float* poses  = (const float*)d_in[3];
    float*       out    = (float*)d_out;

    setup_kernel<<<NBT, 64>>>(meshes, K, idxs, poses);
    bin_kernel<<<(NBATCH * NTILE * 32 + 255) / 256, 256>>>();

    dim3 g(NTILE, BLKSPT, NBATCH);
    gather_kernel<<<g, 64>>>(out);
}

// round 17
// speedup vs baseline: 1.2664x; 1.2664x over previous
#include <cuda_runtime.h>
#include <math.h>

#define RES      256
#define NTRI     1000
#define NBATCH   2
#define NBT      (NBATCH * NTRI)
#define EPSF     1e-8f
#define NPIX     (RES * RES)
#define NPAIR    (NPIX / 2)          // y-pairs packed in u64
#define SCALEF   2097152.0f          // 2^21
#define INVSCALE (1.0f / 2097152.0f)
#define YSPLIT   2                   // scatter blocks per triangle

// accumulator: low 32 = y even, high 32 = y odd. addr = b*NPAIR + x*128 + (y>>1)
// Zero at module load; finalize re-zeros every launch.
__device__ unsigned long long g_accum[NBATCH * NPAIR];

// raw params: [0]={A0,B0,C0,A1} [1]={B1,C1,A2,B2} [2]={C2,mn,inv,0} [3]={iB0,iB1,iB2,0}
__device__ float4 g_q[NBT * 4];
// normalized params: [0]={nA0,nB0,nC0,nA1} [1]={nB1,nC1,nA2,nB2} [2]={nC2,niB0,niB1,niB2}
__device__ float4 g_n[NBT * 3];
__device__ int4   g_bb[NBT];

// exact score evaluation — the SAME raw formula everywhere
__device__ __forceinline__ float eval9(float A0,float B0,float C0,
                                       float A1,float B1,float C1,
                                       float A2,float B2,float C2,
                                       float fx,float fy)
{
    float t0 = fmaxf(fmaf(C0, fy, fmaf(B0, fx, A0)), 0.0f);
    float t1 = fmaxf(fmaf(C1, fy, fmaf(B1, fx, A1)), 0.0f);
    float t2 = fmaxf(fmaf(C2, fy, fmaf(B2, fx, A2)), 0.0f);
    return t0 * t1 * t2;
}

__device__ __forceinline__ float eval_raw(const float4 c0, const float4 c1,
                                          const float4 c2, float fx, float fy)
{
    return eval9(c0.x, c0.y, c0.z, c0.w, c1.x, c1.y, c1.z, c1.w, c2.x, fx, fy);
}

// (5,4) continued-fraction Pade tanh, err <= ~2.4e-5 on [0, 1.05]
__device__ __forceinline__ float tanh_pade(float x)
{
    float t   = x * x;
    float num = fmaf(t, fmaf(t, 1.0f, 105.0f), 945.0f);
    float den = fmaf(t, fmaf(t, 15.0f, 420.0f), 945.0f);
    return x * __fdividef(num, den);
}

// positive interval via precomputed reciprocals; empty -> lo > hi
__device__ __forceinline__ void iv3(float B0, float B1, float B2,
                                    float iB0, float iB1, float iB2,
                                    float r0, float r1, float r2,
                                    float& lo, float& hi)
{
    lo = -1e30f; hi = 1e30f;
    if (B0 >  1e-25f)      lo = -r0 * iB0;
    else if (B0 < -1e-25f) hi = -r0 * iB0;
    else if (r0 <= 0.0f) { lo = 1e30f; hi = -1e30f; return; }
    if (B1 >  1e-25f)      lo = fmaxf(lo, -r1 * iB1);
    else if (B1 < -1e-25f) hi = fminf(hi, -r1 * iB1);
    else if (r1 <= 0.0f) { lo = 1e30f; hi = -1e30f; return; }
    if (B2 >  1e-25f)      lo = fmaxf(lo, -r2 * iB2);
    else if (B2 < -1e-25f) hi = fminf(hi, -r2 * iB2);
    else if (r2 <= 0.0f) { lo = 1e30f; hi = -1e30f; return; }
}

// ---------------------------------------------------------------------------
// Kernel 1: coefficients. ONE THREAD per (b,t) — no redundant lanes.
// ---------------------------------------------------------------------------
__global__ void __launch_bounds__(256) coef_kernel(const float* __restrict__ meshes,
                                                   const float* __restrict__ K,
                                                   const int*   __restrict__ model_idxs,
                                                   const float* __restrict__ poses)
{
    const int bt = blockIdx.x * blockDim.x + threadIdx.x;
    if (bt >= NBT) return;
    const int b = bt / NTRI;
    const int t = bt - b * NTRI;

    float M[12];
    const float* cam = poses + b * 12;
    #pragma unroll
    for (int r = 0; r < 3; r++)
        #pragma unroll
        for (int cc = 0; cc < 4; cc++) {
            float s = 0.0f;
            #pragma unroll
            for (int k = 0; k < 3; k++)
                s += K[r * 3 + k] * cam[k * 4 + cc];
            M[r * 4 + cc] = s;
        }

    const float* mesh = meshes + ((size_t)model_idxs[b] * NTRI + t) * 9;
    float vx[3], vy[3];
    #pragma unroll
    for (int j = 0; j < 3; j++) {
        float X = mesh[j*3+0], Y = mesh[j*3+1], Z = mesh[j*3+2];
        float x = M[0]*X + M[1]*Y + M[2] *Z + M[3];
        float y = M[4]*X + M[5]*Y + M[6] *Z + M[7];
        float w = M[8]*X + M[9]*Y + M[10]*Z + M[11];
        float iw = 1.0f / (w + EPSF);
        vx[j] = x * iw;  vy[j] = y * iw;
    }

    const float e0x = vx[1]-vx[0], e0y = vy[1]-vy[0];
    const float e1x = vx[2]-vx[1], e1y = vy[2]-vy[1];
    const float e2x = vx[0]-vx[2], e2y = vy[0]-vy[2];
    const float N = e0x * e2y - e0y * e2x + EPSF;

    const float A0 = N*(e0x*vy[0]-e0y*vx[0]), B0 =  N*e0y, C0 = -N*e0x;
    const float A1 = N*(e1x*vy[1]-e1y*vx[1]), B1 =  N*e1y, C1 = -N*e1x;
    const float A2 = N*(e2x*vy[2]-e2y*vx[2]), B2 =  N*e2y, C2 = -N*e2x;

    // interior flag: all terms strictly positive at all 4 image corners
    bool inter = true;
    #pragma unroll
    for (int k = 0; k < 4; k++) {
        float cx = (k & 1) ? (float)(RES-1) : 0.0f;
        float cy = (k & 2) ? (float)(RES-1) : 0.0f;
        inter = inter && (fmaf(C0, cy, fmaf(B0, cx, A0)) > 0.0f)
                      && (fmaf(C1, cy, fmaf(B1, cx, A1)) > 0.0f)
                      && (fmaf(C2, cy, fmaf(B2, cx, A2)) > 0.0f);
    }

    // conservative bbox (+1px), clipped; degenerate -> full image
    float fx0 = fminf(fminf(vx[0],vx[1]),vx[2]) - 1.0f;
    float fx1 = fmaxf(fmaxf(vx[0],vx[1]),vx[2]) + 1.0f;
    float fy0 = fminf(fminf(vy[0],vy[1]),vy[2]) - 1.0f;
    float fy1 = fmaxf(fmaxf(vy[0],vy[1]),vy[2]) + 1.0f;
    bool safe = isfinite(fx0) && isfinite(fx1) && isfinite(fy0) && isfinite(fy1)
                && fabsf(N) > 1e-6f;
    int4 bb;
    if (safe) {
        int x0 = (fx0 < 0.0f) ? 0 : ((fx0 > (float)(RES-1)) ? RES : (int)fx0);
        int x1 = (fx1 > (float)(RES-1)) ? (RES-1) : ((fx1 < 0.0f) ? -1 : (int)fx1);
        int y0 = (fy0 < 0.0f) ? 0 : ((fy0 > (float)(RES-1)) ? RES : (int)fy0);
        int y1 = (fy1 > (float)(RES-1)) ? (RES-1) : ((fy1 < 0.0f) ? -1 : (int)fy1);
        if (x0 > x1 || y0 > y1) { x0 = RES; x1 = -1; y0 = RES; y1 = -1; }
        bb = make_int4(x0, x1, y0, y1);
    } else {
        bb = make_int4(0, RES-1, 0, RES-1);
    }

    // interior case: quasi-concave => grid min at an image corner (exact)
    float mn = 0.0f;
    if (inter) {
        const float e = (float)(RES - 1);
        mn = eval9(A0,B0,C0,A1,B1,C1,A2,B2,C2, 0.0f, 0.0f);
        mn = fminf(mn, eval9(A0,B0,C0,A1,B1,C1,A2,B2,C2, e, 0.0f));
        mn = fminf(mn, eval9(A0,B0,C0,A1,B1,C1,A2,B2,C2, 0.0f, e));
        mn = fminf(mn, eval9(A0,B0,C0,A1,B1,C1,A2,B2,C2, e, e));
    }

    // normalized coeffs for root math (scale-invariant)
    float kap = 0.0f;
    kap = fmaxf(kap, fabsf(A0)); kap = fmaxf(kap, 256.0f*fabsf(B0)); kap = fmaxf(kap, 256.0f*fabsf(C0));
    kap = fmaxf(kap, fabsf(A1)); kap = fmaxf(kap, 256.0f*fabsf(B1)); kap = fmaxf(kap, 256.0f*fabsf(C1));
    kap = fmaxf(kap, fabsf(A2)); kap = fmaxf(kap, 256.0f*fabsf(B2)); kap = fmaxf(kap, 256.0f*fabsf(C2));
    float rk = (kap > 1e-30f) ? (1.0f / kap) : 0.0f;
    const float nA0=A0*rk, nB0=B0*rk, nC0=C0*rk;
    const float nA1=A1*rk, nB1=B1*rk, nC1=C1*rk;
    const float nA2=A2*rk, nB2=B2*rk, nC2=C2*rk;

    g_q[bt*4+0] = make_float4(A0, B0, C0, A1);
    g_q[bt*4+1] = make_float4(B1, C1, A2, B2);
    g_q[bt*4+2] = make_float4(C2, mn, 0.0f, 0.0f);
    g_q[bt*4+3] = make_float4(__fdividef(1.0f, B0), __fdividef(1.0f, B1),
                              __fdividef(1.0f, B2), 0.0f);
    g_n[bt*3+0] = make_float4(nA0, nB0, nC0, nA1);
    g_n[bt*3+1] = make_float4(nB1, nC1, nA2, nB2);
    g_n[bt*3+2] = make_float4(nC2, __fdividef(1.0f, nB0),
                              __fdividef(1.0f, nB1), __fdividef(1.0f, nB2));
    g_bb[bt] = bb;
}

// ---------------------------------------------------------------------------
// Kernel 2: analytic bbox max. ONE WARP per (b,t); per-triangle constants
// (reciprocals, pairwise products, i2) hoisted; per-row cost ~1 sqrt.
// ---------------------------------------------------------------------------
__global__ void __launch_bounds__(256) max_kernel()
{
    const int bt = (blockIdx.x * blockDim.x + threadIdx.x) >> 5;
    if (bt >= NBT) return;
    const int lane = threadIdx.x & 31;

    const float4 c0 = g_q[bt*4+0], c1 = g_q[bt*4+1], c2 = g_q[bt*4+2];
    const float4 n0 = g_n[bt*3+0], n1 = g_n[bt*3+1], n2 = g_n[bt*3+2];
    const int4   bb = g_bb[bt];

    const float nA0=n0.x, nB0=n0.y, nC0=n0.z, nA1=n0.w;
    const float nB1=n1.x, nC1=n1.y, nA2=n1.z, nB2=n1.w;
    const float nC2=n2.x, niB0=n2.y, niB1=n2.z, niB2=n2.w;

    const float p01 = nB0*nB1, p02 = nB0*nB2, p12 = nB1*nB2;
    const float q2m = 3.0f * p01 * nB2;
    const bool  quad = fabsf(q2m) > 1e-30f;
    const float i2   = quad ? __fdividef(0.5f, q2m) : 0.0f;
    const float m4   = -4.0f * q2m;

    float mx = 0.0f;
    for (int y = bb.z + lane; y <= bb.w; y += 32) {
        const float fy = (float)y;
        float a0 = fmaf(nC0, fy, nA0);
        float a1 = fmaf(nC1, fy, nA1);
        float a2 = fmaf(nC2, fy, nA2);

        float lo = (float)bb.x, hi = (float)bb.y;
        bool ok = true;
        if (nB0 >  1e-25f)      lo = fmaxf(lo, -a0 * niB0);
        else if (nB0 < -1e-25f) hi = fminf(hi, -a0 * niB0);
        else                    ok = ok && (a0 > 0.0f);
        if (nB1 >  1e-25f)      lo = fmaxf(lo, -a1 * niB1);
        else if (nB1 < -1e-25f) hi = fminf(hi, -a1 * niB1);
        else                    ok = ok && (a1 > 0.0f);
        if (nB2 >  1e-25f)      lo = fmaxf(lo, -a2 * niB2);
        else if (nB2 < -1e-25f) hi = fminf(hi, -a2 * niB2);
        else                    ok = ok && (a2 > 0.0f);

        float clo = ceilf(lo), chi = floorf(hi);
        if (!ok || clo > chi) continue;

        float q1 = 2.0f * fmaf(p01, a2, fmaf(p02, a1, p12 * a0));
        float q0 = fmaf(nB0, a1*a2, fmaf(nB1, a0*a2, nB2*a0*a1));

        float xc1, xc2;
        if (quad) {
            float disc = fmaf(q1, q1, m4 * q0);
            float sq   = sqrtf(fmaxf(disc, 0.0f));
            xc1 = (-q1 + sq) * i2;
            xc2 = (-q1 - sq) * i2;
        } else if (fabsf(q1) > 1e-30f) {
            xc1 = xc2 = -__fdividef(q0, q1);
        } else {
            xc1 = xc2 = 0.5f * (clo + chi);
        }

        float f1 = floorf(xc1), f2 = floorf(xc2);
        float cand[6] = { clo, chi, f1, f1 + 1.0f, f2, f2 + 1.0f };
        #pragma unroll
        for (int i = 0; i < 6; i++) {
            float x = fminf(fmaxf(cand[i], clo), chi);   // NaN-safe
            mx = fmaxf(mx, eval_raw(c0, c1, c2, x, fy));
        }
    }

    #pragma unroll
    for (int o = 16; o > 0; o >>= 1)
        mx = fmaxf(mx, __shfl_xor_sync(0xffffffffu, mx, o));

    if (lane == 0) {
        float inv = 1.0f / (mx - c2.y + EPSF);
        ((float*)(g_q + bt*4 + 2))[2] = inv;
    }
}

// ---------------------------------------------------------------------------
// Kernel 3: scatter (R8 structure). grid = (NBT, YSPLIT), 256 thr (8 warps).
// Warp w of split s handles row-pairs k = k0 + s*8 + w, stride 16.
// Interval roots via precomputed reciprocals (mult, not divide).
// ---------------------------------------------------------------------------
__global__ void __launch_bounds__(256) scatter_kernel()
{
    const int bt   = blockIdx.x;
    const int b    = bt / NTRI;
    const int wid  = threadIdx.x >> 5;
    const int lane = threadIdx.x & 31;

    const int4 bb = g_bb[bt];
    const int k0 = bb.z >> 1;
    const int k1 = bb.w >> 1;
    const int kstart = k0 + (int)blockIdx.y * 8 + wid;
    if (kstart > k1) return;

    const float4 q0 = g_q[bt*4+0];   // A0 B0 C0 A1
    const float4 q1 = g_q[bt*4+1];   // B1 C1 A2 B2
    const float4 q2 = g_q[bt*4+2];   // C2 mn inv -
    const float4 q3 = g_q[bt*4+3];   // iB0 iB1 iB2 -
    const float mn  = q2.y;
    const float inv = q2.z;

    unsigned long long* __restrict__ acc = g_accum + (size_t)b * NPAIR;
    const float flane = (float)lane;

    for (int k = kstart; k <= k1; k += 8 * YSPLIT) {
        const int   y0 = 2 * k, y1 = 2 * k + 1;
        const float fy0 = (float)y0, fy1 = (float)y1;

        // row intercepts
        const float r00 = fmaf(q0.z, fy0, q0.x), r01 = fmaf(q0.z, fy1, q0.x);
        const float r10 = fmaf(q1.y, fy0, q0.w), r11 = fmaf(q1.y, fy1, q0.w);
        const float r20 = fmaf(q2.x, fy0, q1.z), r21 = fmaf(q2.x, fy1, q1.z);

        float lo0, hi0, lo1, hi1;
        iv3(q0.y, q1.x, q1.w, q3.x, q3.y, q3.z, r00, r10, r20, lo0, hi0);
        iv3(q0.y, q1.x, q1.w, q3.x, q3.y, q3.z, r01, r11, r21, lo1, hi1);
        if (y0 < bb.z) { lo0 = 1e30f; hi0 = -1e30f; }
        if (y1 > bb.w) { lo1 = 1e30f; hi1 = -1e30f; }

        float xsf = fmaxf((float)bb.x, ceilf(fminf(lo0, lo1)) - 1.0f);
        float xef = fminf((float)bb.y, floorf(fmaxf(hi0, hi1)) + 1.0f);
        const int xs = (int)xsf;
        const int xe = (int)xef;

        float fx = xsf + flane;
        for (int x = xs + lane; x <= xe; x += 32, fx += 32.0f) {
            float u00 = fmaxf(fmaf(q0.y, fx, r00), 0.0f);
            float u01 = fmaxf(fmaf(q0.y, fx, r01), 0.0f);
            float u10 = fmaxf(fmaf(q1.x, fx, r10), 0.0f);
            float u11 = fmaxf(fmaf(q1.x, fx, r11), 0.0f);
            float u20 = fmaxf(fmaf(q1.w, fx, r20), 0.0f);
            float u21 = fmaxf(fmaf(q1.w, fx, r21), 0.0f);
            float d0  = u00 * u10 * u20 - mn;
            float d1  = u01 * u11 * u21 - mn;
            unsigned int v0 = 0u, v1 = 0u;
            if (d0 > 0.0f) v0 = __float2uint_rn(tanh_pade(d0 * inv) * SCALEF);
            if (d1 > 0.0f) v1 = __float2uint_rn(tanh_pade(d1 * inv) * SCALEF);
            unsigned long long p = (unsigned long long)v0
                                 | ((unsigned long long)v1 << 32);
            if (p) atomicAdd(acc + x * (RES / 2) + k, p);
        }
    }
}

// ---------------------------------------------------------------------------
// Kernel 4: finalize with 4-pair ILP. Unpack fixed point -> float output and
// reset the accumulator for the next graph replay.
// ---------------------------------------------------------------------------
__global__ void __launch_bounds__(256) finalize_kernel(float* __restrict__ out)
{
    const int i4 = blockIdx.x * blockDim.x + threadIdx.x;
    const int i  = i4 * 4;
    if (i >= NBATCH * NPAIR) return;

    ulonglong2 pA = *(ulonglong2*)(g_accum + i);
    ulonglong2 pB = *(ulonglong2*)(g_accum + i + 2);
    *(ulonglong2*)(g_accum + i)     = make_ulonglong2(0ull, 0ull);
    *(ulonglong2*)(g_accum + i + 2) = make_ulonglong2(0ull, 0ull);

    const int b = i / NPAIR;
    const int r = i - b * NPAIR;          // r = x*128 + k, k multiple of 4
    const int x = r >> 7;
    const int k = r & 127;
    float* o = out + (size_t)b * NPIX + x * RES + 2 * k;

    float4 v0, v1;
    v0.x = (float)(unsigned int)(pA.x)       * INVSCALE;
    v0.y = (float)(unsigned int)(pA.x >> 32) * INVSCALE;
    v0.z = (float)(unsigned int)(pA.y)       * INVSCALE;
    v0.w = (float)(unsigned int)(pA.y >> 32) * INVSCALE;
    v1.x = (float)(unsigned int)(pB.x)       * INVSCALE;
    v1.y = (float)(unsigned int)(pB.x >> 32) * INVSCALE;
    v1.z = (float)(unsigned int)(pB.y)       * INVSCALE;
    v1.w = (float)(unsigned int)(pB.y >> 32) * INVSCALE;
    *(float4*)o       = v0;
    *(float4*)(o + 4) = v1;
}

// ---------------------------------------------------------------------------
extern "C" void kernel_launch(void* const* d_in, const int* in_sizes, int n_in,
                              void* d_out, int out_size)
{
    const float* meshes = (const float*)d_in[0];
    const float* K      = (const float*)d_in[1];
    const int*   idxs   = (const int*)  d_in[2];
    const float* poses  = (const float*)d_in[3];
    float*       out    = (float*)d_out;

    coef_kernel<<<(NBT + 255) / 256, 256>>>(meshes, K, idxs, poses);
    max_kernel<<<(NBT * 32 + 255) / 256, 256>>>();

    dim3 g(NBT, YSPLIT);
    scatter_kernel<<<g, 256>>>();

    finalize_kernel<<<(NBATCH * NPAIR / 4 + 255) / 256, 256>>>(out);
}